// round 8
// baseline (speedup 1.0000x reference)
#include <cuda_runtime.h>
#include <cstdint>

// 524288 rows x 65 fp32 (h = row[0], x = row[1..64]); GRU cell + Linear(1,1).
//
// Round-8: perfectly balanced persistent grid.
//   64-row tiles (16,640 B), ring-3 cp.async groups, grid = 512 CTAs
//   (single wave on 148 SMs, <=4/SM) -> 8192/512 = 16 tiles per CTA
//   exactly. Removes the 14-vs-13 tail imbalance of round 7.
//   Measured stream ceiling ~5.3 TB/s; floor at that BW = 26.0 us.

#define ROWS_TOTAL    524288
#define ROW_F         65
#define THREADS       128
#define ROWS_PER_TILE 64
#define NTILES        (ROWS_TOTAL / ROWS_PER_TILE)   // 8192
#define TILE_FLOATS   (ROWS_PER_TILE * ROW_F)        // 4160
#define TILE_Q        (TILE_FLOATS / 4)              // 1040 float4
#define RING          3
#define GRID_CTAS     512                            // 8192 / 512 = 16 exact
#define DYN_SMEM_BYTES ((RING * TILE_FLOATS + 192) * 4)  // 50688

__device__ __forceinline__ uint32_t smem_u32(const void* p) {
    return (uint32_t)__cvta_generic_to_shared(p);
}

// Copy one tile (1040 float4) global->smem via per-thread cp.async,
// committed as one group.
__device__ __forceinline__ void prefetch_tile(float* dst, const float* src,
                                              int tid) {
    const float4* __restrict__ g = (const float4*)src;
    const uint32_t s0 = smem_u32(dst);
    #pragma unroll
    for (int j = 0; j < 9; ++j) {
        const int idx = j * THREADS + tid;
        if (idx < TILE_Q) {
            asm volatile("cp.async.cg.shared.global [%0], [%1], 16;"
                         :: "r"(s0 + (uint32_t)idx * 16u), "l"(g + idx)
                         : "memory");
        }
    }
    asm volatile("cp.async.commit_group;" ::: "memory");
}

__global__ __launch_bounds__(THREADS) void gru_bal_kernel(
    const float* __restrict__ in,      // [ROWS_TOTAL, 65]
    const float* __restrict__ W_ih,    // [3, 64]
    const float* __restrict__ W_hh,    // [3]
    const float* __restrict__ b_ih,    // [3]
    const float* __restrict__ b_hh,    // [3]
    const float* __restrict__ w_out,   // [1]
    const float* __restrict__ b_out,   // [1]
    float* __restrict__ out)           // [ROWS_TOTAL]
{
    extern __shared__ __align__(16) float sdyn[];
    float* const sw = sdyn + RING * TILE_FLOATS;    // 192 floats W_ih

    const int tid = threadIdx.x;

    if (tid < 48) ((float4*)sw)[tid] = ((const float4*)W_ih)[tid];

    // Prologue: prefetch tiles 0 and 1 into slots 0 and 1 (two groups).
    {
        const int t0 = blockIdx.x;
        const int t1 = blockIdx.x + GRID_CTAS;
        prefetch_tile(sdyn, in + (size_t)t0 * TILE_FLOATS, tid);
        prefetch_tile(sdyn + TILE_FLOATS, in + (size_t)t1 * TILE_FLOATS, tid);
    }

    // Uniform scalars (overlap prologue copies).
    const float bi0 = b_ih[0],  bi1 = b_ih[1],  bi2 = b_ih[2];
    const float wh0 = W_hh[0],  wh1 = W_hh[1],  wh2 = W_hh[2];
    const float bh0 = b_hh[0],  bh1 = b_hh[1],  bh2 = b_hh[2];
    const float wo  = w_out[0], bo  = b_out[0];

    int i = 0;
    for (int tile = blockIdx.x; tile < NTILES; tile += GRID_CTAS, ++i) {
        const int s = i % RING;
        float* const bcur = sdyn + s * TILE_FLOATS;

        // Issue tile i+2 into slot (i+2)%RING; wait so that slot s's group
        // (2 groups older than the just-issued one) is complete.
        const int n2 = tile + 2 * GRID_CTAS;
        if (n2 < NTILES) {
            prefetch_tile(sdyn + ((i + 2) % RING) * TILE_FLOATS,
                          in + (size_t)n2 * TILE_FLOATS, tid);
            asm volatile("cp.async.wait_group 2;" ::: "memory");
        } else {
            asm volatile("cp.async.wait_group 0;" ::: "memory");
        }
        __syncthreads();   // slot s visible to all threads

        if (tid < ROWS_PER_TILE) {
            // ---- compute: thread t owns row t of this tile ----
            const float* __restrict__ xr = bcur + tid * ROW_F;
            const float h = xr[0];

            float s0 = 0.f, s1 = 0.f, s2 = 0.f;
            const float4* __restrict__ swq = (const float4*)sw;
            #pragma unroll
            for (int c = 0; c < 16; ++c) {
                const float4 w0 = swq[c];
                const float4 w1 = swq[16 + c];
                const float4 w2 = swq[32 + c];
                const float a0 = xr[1 + 4 * c + 0];
                const float a1 = xr[1 + 4 * c + 1];
                const float a2 = xr[1 + 4 * c + 2];
                const float a3 = xr[1 + 4 * c + 3];
                s0 = fmaf(a0, w0.x, fmaf(a1, w0.y, fmaf(a2, w0.z, fmaf(a3, w0.w, s0))));
                s1 = fmaf(a0, w1.x, fmaf(a1, w1.y, fmaf(a2, w1.z, fmaf(a3, w1.w, s1))));
                s2 = fmaf(a0, w2.x, fmaf(a1, w2.y, fmaf(a2, w2.z, fmaf(a3, w2.w, s2))));
            }

            const float gi0 = s0 + bi0;
            const float gi1 = s1 + bi1;
            const float gi2 = s2 + bi2;
            const float gh0 = fmaf(h, wh0, bh0);
            const float gh1 = fmaf(h, wh1, bh1);
            const float gh2 = fmaf(h, wh2, bh2);

            const float r = 1.0f / (1.0f + expf(-(gi0 + gh0)));
            const float z = 1.0f / (1.0f + expf(-(gi1 + gh1)));
            const float n = tanhf(fmaf(r, gh2, gi2));
            const float h_new = fmaf(z, h - n, n);   // (1-z)*n + z*h

            out[tile * ROWS_PER_TILE + tid] = fmaf(h_new, wo, bo);
        }

        // Slot s fully consumed before iteration i+1 issues tile i+3 into it.
        __syncthreads();
    }
}

extern "C" void kernel_launch(void* const* d_in, const int* in_sizes, int n_in,
                              void* d_out, int out_size) {
    const float* inputs = (const float*)d_in[0];
    const float* W_ih   = (const float*)d_in[1];
    const float* W_hh   = (const float*)d_in[2];
    const float* b_ih   = (const float*)d_in[3];
    const float* b_hh   = (const float*)d_in[4];
    const float* w_out  = (const float*)d_in[5];
    const float* b_out  = (const float*)d_in[6];
    float* out = (float*)d_out;

    cudaFuncSetAttribute(gru_bal_kernel,
                         cudaFuncAttributeMaxDynamicSharedMemorySize,
                         DYN_SMEM_BYTES);
    gru_bal_kernel<<<GRID_CTAS, THREADS, DYN_SMEM_BYTES>>>(
        inputs, W_ih, W_hh, b_ih, b_hh, w_out, b_out, out);
}

// round 10
// speedup vs baseline: 1.0100x; 1.0100x over previous
#include <cuda_runtime.h>
#include <cstdint>

// 524288 rows x 65 fp32 (h = row[0], x = row[1..64]); GRU cell + Linear(1,1).
//
// Round-9 (resubmit; infra failed last round): max chip-level concurrency.
// 64-row tiles (16,640 B), ring-2 cp.async groups (33.5 KB smem) ->
// 6 CTAs/SM, grid = 888. Same proven issue-next/wait_group/compute loop as
// round 7 (best: 27.9 us). Floor at measured 5.3 TB/s stream BW = 26.0 us.

#define ROWS_TOTAL    524288
#define ROW_F         65
#define THREADS       128
#define ROWS_PER_TILE 64
#define NTILES        (ROWS_TOTAL / ROWS_PER_TILE)   // 8192
#define TILE_FLOATS   (ROWS_PER_TILE * ROW_F)        // 4160
#define TILE_Q        (TILE_FLOATS / 4)              // 1040 float4
#define RING          2
#define GRID_CTAS     888                            // 148 * 6
#define DYN_SMEM_BYTES ((RING * TILE_FLOATS + 192) * 4)  // 34048

__device__ __forceinline__ uint32_t smem_u32(const void* p) {
    return (uint32_t)__cvta_generic_to_shared(p);
}

// Copy one tile (1040 float4) global->smem via per-thread cp.async,
// committed as one group.
__device__ __forceinline__ void prefetch_tile(float* dst, const float* src,
                                              int tid) {
    const float4* __restrict__ g = (const float4*)src;
    const uint32_t s0 = smem_u32(dst);
    #pragma unroll
    for (int j = 0; j < 9; ++j) {
        const int idx = j * THREADS + tid;
        if (idx < TILE_Q) {
            asm volatile("cp.async.cg.shared.global [%0], [%1], 16;"
                         :: "r"(s0 + (uint32_t)idx * 16u), "l"(g + idx)
                         : "memory");
        }
    }
    asm volatile("cp.async.commit_group;" ::: "memory");
}

__global__ __launch_bounds__(THREADS) void gru_conc_kernel(
    const float* __restrict__ in,      // [ROWS_TOTAL, 65]
    const float* __restrict__ W_ih,    // [3, 64]
    const float* __restrict__ W_hh,    // [3]
    const float* __restrict__ b_ih,    // [3]
    const float* __restrict__ b_hh,    // [3]
    const float* __restrict__ w_out,   // [1]
    const float* __restrict__ b_out,   // [1]
    float* __restrict__ out)           // [ROWS_TOTAL]
{
    extern __shared__ __align__(16) float sdyn[];
    float* const sw = sdyn + RING * TILE_FLOATS;    // 192 floats W_ih

    const int tid = threadIdx.x;

    if (tid < 48) ((float4*)sw)[tid] = ((const float4*)W_ih)[tid];

    // Prologue: prefetch first tile into slot 0 (one group).
    prefetch_tile(sdyn, in + (size_t)blockIdx.x * TILE_FLOATS, tid);

    // Uniform scalars (overlap prologue copy).
    const float bi0 = b_ih[0],  bi1 = b_ih[1],  bi2 = b_ih[2];
    const float wh0 = W_hh[0],  wh1 = W_hh[1],  wh2 = W_hh[2];
    const float bh0 = b_hh[0],  bh1 = b_hh[1],  bh2 = b_hh[2];
    const float wo  = w_out[0], bo  = b_out[0];

    int i = 0;
    for (int tile = blockIdx.x; tile < NTILES; tile += GRID_CTAS, ++i) {
        const int cur = i & 1;
        float* const bcur = sdyn + cur * TILE_FLOATS;

        // Issue tile i+1 into the other slot (fully consumed last iter,
        // barrier at loop bottom), then wait so slot cur's group is done.
        const int nxt = tile + GRID_CTAS;
        if (nxt < NTILES) {
            prefetch_tile(sdyn + (1 - cur) * TILE_FLOATS,
                          in + (size_t)nxt * TILE_FLOATS, tid);
            asm volatile("cp.async.wait_group 1;" ::: "memory");
        } else {
            asm volatile("cp.async.wait_group 0;" ::: "memory");
        }
        __syncthreads();   // slot cur visible to all threads

        if (tid < ROWS_PER_TILE) {
            // ---- compute: thread t owns row t of this tile ----
            const float* __restrict__ xr = bcur + tid * ROW_F;
            const float h = xr[0];

            float s0 = 0.f, s1 = 0.f, s2 = 0.f;
            const float4* __restrict__ swq = (const float4*)sw;
            #pragma unroll
            for (int c = 0; c < 16; ++c) {
                const float4 w0 = swq[c];
                const float4 w1 = swq[16 + c];
                const float4 w2 = swq[32 + c];
                const float a0 = xr[1 + 4 * c + 0];
                const float a1 = xr[1 + 4 * c + 1];
                const float a2 = xr[1 + 4 * c + 2];
                const float a3 = xr[1 + 4 * c + 3];
                s0 = fmaf(a0, w0.x, fmaf(a1, w0.y, fmaf(a2, w0.z, fmaf(a3, w0.w, s0))));
                s1 = fmaf(a0, w1.x, fmaf(a1, w1.y, fmaf(a2, w1.z, fmaf(a3, w1.w, s1))));
                s2 = fmaf(a0, w2.x, fmaf(a1, w2.y, fmaf(a2, w2.z, fmaf(a3, w2.w, s2))));
            }

            const float gi0 = s0 + bi0;
            const float gi1 = s1 + bi1;
            const float gi2 = s2 + bi2;
            const float gh0 = fmaf(h, wh0, bh0);
            const float gh1 = fmaf(h, wh1, bh1);
            const float gh2 = fmaf(h, wh2, bh2);

            const float r = 1.0f / (1.0f + expf(-(gi0 + gh0)));
            const float z = 1.0f / (1.0f + expf(-(gi1 + gh1)));
            const float n = tanhf(fmaf(r, gh2, gi2));
            const float h_new = fmaf(z, h - n, n);   // (1-z)*n + z*h

            out[tile * ROWS_PER_TILE + tid] = fmaf(h_new, wo, bo);
        }

        // Slot cur fully consumed before next iteration overwrites it.
        __syncthreads();
    }
}

extern "C" void kernel_launch(void* const* d_in, const int* in_sizes, int n_in,
                              void* d_out, int out_size) {
    const float* inputs = (const float*)d_in[0];
    const float* W_ih   = (const float*)d_in[1];
    const float* W_hh   = (const float*)d_in[2];
    const float* b_ih   = (const float*)d_in[3];
    const float* b_hh   = (const float*)d_in[4];
    const float* w_out  = (const float*)d_in[5];
    const float* b_out  = (const float*)d_in[6];
    float* out = (float*)d_out;

    cudaFuncSetAttribute(gru_conc_kernel,
                         cudaFuncAttributeMaxDynamicSharedMemorySize,
                         DYN_SMEM_BYTES);
    gru_conc_kernel<<<GRID_CTAS, THREADS, DYN_SMEM_BYTES>>>(
        inputs, W_ih, W_hh, b_ih, b_hh, w_out, b_out, out);
}

// round 11
// speedup vs baseline: 1.0499x; 1.0394x over previous
#include <cuda_runtime.h>
#include <cstdint>

// 524288 rows x 65 fp32 (h = row[0], x = row[1..64]); GRU cell + Linear(1,1).
//
// Final config (= round-7 empirical best, 27.9 us):
//   64-row tiles (16,640 B), ring-3 cp.async groups -> 2 tiles in flight
//   per CTA during compute, grid = 592 (148 SMs x 4 CTAs @ ~50 KB smem).
//   Thread-per-row compute from smem (stride-65 = conflict-free banks).
// Measured stream ceiling ~5.3 TB/s; device-time floor 26.0 us; this
// config's device time 26.6 us (within 2.4%).

#define ROWS_TOTAL    524288
#define ROW_F         65
#define THREADS       128
#define ROWS_PER_TILE 64
#define NTILES        (ROWS_TOTAL / ROWS_PER_TILE)   // 8192
#define TILE_FLOATS   (ROWS_PER_TILE * ROW_F)        // 4160
#define TILE_Q        (TILE_FLOATS / 4)              // 1040 float4
#define RING          3
#define GRID_CTAS     592                            // 148 * 4
#define DYN_SMEM_BYTES ((RING * TILE_FLOATS + 192) * 4)  // 50688

__device__ __forceinline__ uint32_t smem_u32(const void* p) {
    return (uint32_t)__cvta_generic_to_shared(p);
}

// Copy one tile (1040 float4) global->smem via per-thread cp.async,
// committed as one group. 1040 = 8*128 + 16: eight unconditional waves,
// one 16-lane remainder (no per-iteration predicate).
__device__ __forceinline__ void prefetch_tile(float* dst, const float* src,
                                              int tid) {
    const float4* __restrict__ g = (const float4*)src;
    const uint32_t s0 = smem_u32(dst);
    #pragma unroll
    for (int j = 0; j < 8; ++j) {
        const int idx = j * THREADS + tid;
        asm volatile("cp.async.cg.shared.global [%0], [%1], 16;"
                     :: "r"(s0 + (uint32_t)idx * 16u), "l"(g + idx)
                     : "memory");
    }
    if (tid < TILE_Q - 8 * THREADS) {   // 16 lanes
        const int idx = 8 * THREADS + tid;
        asm volatile("cp.async.cg.shared.global [%0], [%1], 16;"
                     :: "r"(s0 + (uint32_t)idx * 16u), "l"(g + idx)
                     : "memory");
    }
    asm volatile("cp.async.commit_group;" ::: "memory");
}

__global__ __launch_bounds__(THREADS) void gru_final_kernel(
    const float* __restrict__ in,      // [ROWS_TOTAL, 65]
    const float* __restrict__ W_ih,    // [3, 64]
    const float* __restrict__ W_hh,    // [3]
    const float* __restrict__ b_ih,    // [3]
    const float* __restrict__ b_hh,    // [3]
    const float* __restrict__ w_out,   // [1]
    const float* __restrict__ b_out,   // [1]
    float* __restrict__ out)           // [ROWS_TOTAL]
{
    extern __shared__ __align__(16) float sdyn[];
    float* const sw = sdyn + RING * TILE_FLOATS;    // 192 floats W_ih

    const int tid = threadIdx.x;

    if (tid < 48) ((float4*)sw)[tid] = ((const float4*)W_ih)[tid];

    // Prologue: prefetch tiles 0 and 1 into slots 0 and 1 (two groups).
    {
        const int t0 = blockIdx.x;
        const int t1 = blockIdx.x + GRID_CTAS;
        prefetch_tile(sdyn, in + (size_t)t0 * TILE_FLOATS, tid);
        if (t1 < NTILES)
            prefetch_tile(sdyn + TILE_FLOATS, in + (size_t)t1 * TILE_FLOATS, tid);
    }

    // Uniform scalars (overlap prologue copies).
    const float bi0 = b_ih[0],  bi1 = b_ih[1],  bi2 = b_ih[2];
    const float wh0 = W_hh[0],  wh1 = W_hh[1],  wh2 = W_hh[2];
    const float bh0 = b_hh[0],  bh1 = b_hh[1],  bh2 = b_hh[2];
    const float wo  = w_out[0], bo  = b_out[0];

    int i = 0;
    for (int tile = blockIdx.x; tile < NTILES; tile += GRID_CTAS, ++i) {
        const int s = i % RING;
        float* const bcur = sdyn + s * TILE_FLOATS;

        // Issue tile i+2 into slot (i+2)%RING; wait so that slot s's group
        // (2 groups older than the just-issued one) is complete.
        const int n2 = tile + 2 * GRID_CTAS;
        if (n2 < NTILES) {
            prefetch_tile(sdyn + ((i + 2) % RING) * TILE_FLOATS,
                          in + (size_t)n2 * TILE_FLOATS, tid);
            asm volatile("cp.async.wait_group 2;" ::: "memory");
        } else {
            asm volatile("cp.async.wait_group 0;" ::: "memory");
        }
        __syncthreads();   // slot s visible to all threads

        if (tid < ROWS_PER_TILE) {
            // ---- compute: thread t owns row t of this tile ----
            const float* __restrict__ xr = bcur + tid * ROW_F;
            const float h = xr[0];

            float s0 = 0.f, s1 = 0.f, s2 = 0.f;
            const float4* __restrict__ swq = (const float4*)sw;
            #pragma unroll
            for (int c = 0; c < 16; ++c) {
                const float4 w0 = swq[c];
                const float4 w1 = swq[16 + c];
                const float4 w2 = swq[32 + c];
                const float a0 = xr[1 + 4 * c + 0];
                const float a1 = xr[1 + 4 * c + 1];
                const float a2 = xr[1 + 4 * c + 2];
                const float a3 = xr[1 + 4 * c + 3];
                s0 = fmaf(a0, w0.x, fmaf(a1, w0.y, fmaf(a2, w0.z, fmaf(a3, w0.w, s0))));
                s1 = fmaf(a0, w1.x, fmaf(a1, w1.y, fmaf(a2, w1.z, fmaf(a3, w1.w, s1))));
                s2 = fmaf(a0, w2.x, fmaf(a1, w2.y, fmaf(a2, w2.z, fmaf(a3, w2.w, s2))));
            }

            const float gi0 = s0 + bi0;
            const float gi1 = s1 + bi1;
            const float gi2 = s2 + bi2;
            const float gh0 = fmaf(h, wh0, bh0);
            const float gh1 = fmaf(h, wh1, bh1);
            const float gh2 = fmaf(h, wh2, bh2);

            const float r = 1.0f / (1.0f + expf(-(gi0 + gh0)));
            const float z = 1.0f / (1.0f + expf(-(gi1 + gh1)));
            const float n = tanhf(fmaf(r, gh2, gi2));
            const float h_new = fmaf(z, h - n, n);   // (1-z)*n + z*h

            out[tile * ROWS_PER_TILE + tid] = fmaf(h_new, wo, bo);
        }

        // Slot s fully consumed before iteration i+1 issues tile i+3 into it.
        __syncthreads();
    }
}

extern "C" void kernel_launch(void* const* d_in, const int* in_sizes, int n_in,
                              void* d_out, int out_size) {
    const float* inputs = (const float*)d_in[0];
    const float* W_ih   = (const float*)d_in[1];
    const float* W_hh   = (const float*)d_in[2];
    const float* b_ih   = (const float*)d_in[3];
    const float* b_hh   = (const float*)d_in[4];
    const float* w_out  = (const float*)d_in[5];
    const float* b_out  = (const float*)d_in[6];
    float* out = (float*)d_out;

    cudaFuncSetAttribute(gru_final_kernel,
                         cudaFuncAttributeMaxDynamicSharedMemorySize,
                         DYN_SMEM_BYTES);
    gru_final_kernel<<<GRID_CTAS, THREADS, DYN_SMEM_BYTES>>>(
        inputs, W_ih, W_hh, b_ih, b_hh, w_out, b_out, out);
}